// round 4
// baseline (speedup 1.0000x reference)
#include <cuda_runtime.h>

typedef unsigned long long ull;

#define B_   256
#define T_   1000
#define H_   512
#define NTN  16          // column tiles (32 cols each)
#define NTM  8           // batch tiles (32 batches each)
#define NCTA (NTN*NTM)   // 128
#define NTHR 256
#define KC   128         // K chunk staged in smem
#define NCH  (H_/KC)     // 4
#define HS_STRIDE 132    // padded row stride (floats) for h chunk

// shared memory layout (float offsets)
#define OFF_WZ    0
#define OFF_WR    16384
#define OFF_WH    32768
#define OFF_HS    49152
#define OFF_SMALL (OFF_HS + 32*HS_STRIDE)       // 53376
#define SMEM_FLOATS (OFF_SMALL + 9*32)          // 53664
#define SMEM_BYTES (SMEM_FLOATS*4)              // 214656

// persistent device state (reset every launch by init_kernel / first step)
__device__ float g_hr[B_*H_];
__device__ float g_k[B_];
__device__ float g_kpart[NTN*B_];
__device__ volatile unsigned g_arrive[NTM*16];
__device__ volatile unsigned g_release[NTM*32];

// ---- packed f32x2 helpers (Blackwell FFMA2 via PTX) ----
__device__ __forceinline__ ull pack2(float lo, float hi){ ull r; asm("mov.b64 %0,{%1,%2};":"=l"(r):"f"(lo),"f"(hi)); return r; }
__device__ __forceinline__ ull splat(float x){ return pack2(x, x); }
__device__ __forceinline__ void unpack2(ull v, float& lo, float& hi){ asm("mov.b64 {%0,%1},%2;":"=f"(lo),"=f"(hi):"l"(v)); }
__device__ __forceinline__ ull fma2(ull a, ull b, ull c){ ull d; asm("fma.rn.f32x2 %0,%1,%2,%3;":"=l"(d):"l"(a),"l"(b),"l"(c)); return d; }
__device__ __forceinline__ ull add2(ull a, ull b){ ull d; asm("add.rn.f32x2 %0,%1,%2;":"=l"(d):"l"(a),"l"(b)); return d; }

__device__ __forceinline__ float sigm(float x){ return 1.0f/(1.0f+__expf(-x)); }

// 16-CTA group barrier (per batch-tile group); epoch-based, reset by init_kernel
__device__ __forceinline__ void group_barrier(int grp, int mem, unsigned ep){
    __threadfence();
    __syncthreads();
    if (threadIdx.x == 0){
        if (mem == 0){
            #pragma unroll 1
            for (int i = 1; i < 16; i++){
                while (g_arrive[grp*16 + i] < ep) { }
            }
            __threadfence();
            g_release[grp*32] = ep;
        } else {
            g_arrive[grp*16 + mem] = ep;
            while (g_release[grp*32] < ep) { }
        }
    }
    __syncthreads();
}

__global__ void init_kernel(){
    int i = threadIdx.x;
    if (i < NTM*16) g_arrive[i] = 0u;
    if (i < NTM*32) g_release[i] = 0u;
}

__global__ void __launch_bounds__(NTHR, 1) mcgru_kernel(
    const float* __restrict__ inp, const float* __restrict__ St, const float* __restrict__ Mass,
    const float* __restrict__ Wz, const float* __restrict__ bz,
    const float* __restrict__ Wr, const float* __restrict__ br,
    const float* __restrict__ Wh, const float* __restrict__ bh,
    const float* __restrict__ Wk, const float* __restrict__ bk,
    float* __restrict__ out)
{
    extern __shared__ float sm[];
    float* WzS = sm + OFF_WZ;
    float* WrS = sm + OFF_WR;
    float* WhS = sm + OFF_WH;
    float* hS  = sm + OFF_HS;
    float* sml = sm + OFF_SMALL;
    float* vz0s = sml;        float* vr0s  = sml + 32;  float* vh0s  = sml + 64;
    float* vh513s = sml + 96; float* vh514s = sml + 128;
    float* bzs = sml + 160;   float* brs = sml + 192;   float* bhs = sml + 224;
    float* wks = sml + 256;

    const int tid   = threadIdx.x;
    const int tileN = blockIdx.x & (NTN-1);
    const int tileM = blockIdx.x >> 4;
    const int c0    = tileN * 32;
    const int p     = tid & 15;          // column-pair index (16 pairs = 32 cols)
    const int bg    = tid >> 4;          // 0..15
    const int bl0   = bg, bl1 = bg + 16; // local batches
    const int gb0   = tileM*32 + bl0, gb1 = tileM*32 + bl1;
    const int jp    = 2*p;

    // ---- prologue: stage weight slices into SMEM ----
    for (int i = tid; i < 512*32; i += NTHR){
        int k = i >> 5, c = i & 31;
        WzS[i] = Wz[(k+1)*H_ + c0 + c];
        WrS[i] = Wr[(k+1)*H_ + c0 + c];
        WhS[i] = Wh[(k+1)*H_ + c0 + c];
    }
    if (tid < 32){
        vz0s[tid]   = Wz[c0 + tid];
        vr0s[tid]   = Wr[c0 + tid];
        vh0s[tid]   = Wh[c0 + tid];
        vh513s[tid] = Wh[513*H_ + c0 + tid];
        vh514s[tid] = Wh[514*H_ + c0 + tid];
        bzs[tid]    = bz[c0 + tid];
        brs[tid]    = br[c0 + tid];
        bhs[tid]    = bh[c0 + tid];
        wks[tid]    = Wk[c0 + tid];
    }
    const float st0 = St[gb0],  st1 = St[gb1];
    const float ms0 = Mass[gb0], ms1 = Mass[gb1];
    __syncthreads();

    const ull vz0p   = *(const ull*)(vz0s + jp);
    const ull vr0p   = *(const ull*)(vr0s + jp);
    const ull vh0p   = *(const ull*)(vh0s + jp);
    const ull vh513p = *(const ull*)(vh513s + jp);
    const ull vh514p = *(const ull*)(vh514s + jp);
    const ull bzp    = *(const ull*)(bzs + jp);
    const ull brp    = *(const ull*)(brs + jp);
    const ull bhp    = *(const ull*)(bhs + jp);
    float wk0, wk1;  unpack2(*(const ull*)(wks + jp), wk0, wk1);

    const float* h0p = hS + bl0*HS_STRIDE;
    const float* h1p = hS + bl1*HS_STRIDE;

    float kreg = 0.0f;   // leader-tile register copy of k (tileN==0, tid<32)
    unsigned ep = 0;

    #pragma unroll 1
    for (int t = 0; t < T_; t++){
        // ---- k finalize: k_{t-1} from step t-1 partials (leader column-tile) ----
        if (tileN == 0 && tid < 32){
            int gb = tileM*32 + tid;
            if (t == 0){
                kreg = 0.0f;
            } else {
                float s = kreg * __ldg(&Wk[H_]) + __ldg(&bk[0]);
                #pragma unroll
                for (int n = 0; n < NTN; n++) s += __ldcg(&g_kpart[n*B_ + gb]);
                kreg = sigm(s);
            }
            g_k[gb] = kreg;
        }

        const float xb0 = __ldg(inp + gb0*T_ + t);
        const float xb1 = __ldg(inp + gb1*T_ + t);

        // ---- phase 1: z, r = sigmoid([x, h_{t-1}] @ W + b) ----
        ull az0 = 0, az1 = 0, ar0 = 0, ar1 = 0;
        float2 ho0 = make_float2(0.f, 0.f), ho1 = make_float2(0.f, 0.f);

        if (t > 0){
            const float* base1 = out + (tileM*32)*(T_*H_) + (t-1)*H_;
            float4 pf[4];
            #pragma unroll
            for (int u = 0; u < 4; u++){
                int i = tid + u*NTHR; int row = i >> 5, c4 = (i & 31)*4;
                pf[u] = __ldcg((const float4*)(base1 + row*(T_*H_) + c4));
            }
            #pragma unroll 1
            for (int ch = 0; ch < NCH; ch++){
                #pragma unroll
                for (int u = 0; u < 4; u++){
                    int i = tid + u*NTHR; int row = i >> 5, c4 = (i & 31)*4;
                    *(float4*)(hS + row*HS_STRIDE + c4) = pf[u];
                }
                __syncthreads();
                if (ch < NCH-1){
                    int kc = (ch+1)*KC;
                    #pragma unroll
                    for (int u = 0; u < 4; u++){
                        int i = tid + u*NTHR; int row = i >> 5, c4 = (i & 31)*4;
                        pf[u] = __ldcg((const float4*)(base1 + row*(T_*H_) + kc + c4));
                    }
                }
                const ull* wzp = (const ull*)(WzS + ch*KC*32) + p;
                const ull* wrp = (const ull*)(WrS + ch*KC*32) + p;
                #pragma unroll 4
                for (int kk = 0; kk < KC; kk += 4){
                    float4 ha = *(const float4*)(h0p + kk);
                    float4 hb = *(const float4*)(h1p + kk);
                    ull wz, wr, pa, pb;
                    wz = wzp[(kk+0)*16]; wr = wrp[(kk+0)*16]; pa = splat(ha.x); pb = splat(hb.x);
                    az0=fma2(pa,wz,az0); az1=fma2(pb,wz,az1); ar0=fma2(pa,wr,ar0); ar1=fma2(pb,wr,ar1);
                    wz = wzp[(kk+1)*16]; wr = wrp[(kk+1)*16]; pa = splat(ha.y); pb = splat(hb.y);
                    az0=fma2(pa,wz,az0); az1=fma2(pb,wz,az1); ar0=fma2(pa,wr,ar0); ar1=fma2(pb,wr,ar1);
                    wz = wzp[(kk+2)*16]; wr = wrp[(kk+2)*16]; pa = splat(ha.z); pb = splat(hb.z);
                    az0=fma2(pa,wz,az0); az1=fma2(pb,wz,az1); ar0=fma2(pa,wr,ar0); ar1=fma2(pb,wr,ar1);
                    wz = wzp[(kk+3)*16]; wr = wrp[(kk+3)*16]; pa = splat(ha.w); pb = splat(hb.w);
                    az0=fma2(pa,wz,az0); az1=fma2(pb,wz,az1); ar0=fma2(pa,wr,ar0); ar1=fma2(pb,wr,ar1);
                }
                __syncthreads();
            }
            ho0 = *(const float2*)(out + (gb0*T_ + (t-1))*H_ + c0 + jp);
            ho1 = *(const float2*)(out + (gb1*T_ + (t-1))*H_ + c0 + jp);
        }

        az0 = add2(fma2(splat(xb0), vz0p, az0), bzp);
        az1 = add2(fma2(splat(xb1), vz0p, az1), bzp);
        ar0 = add2(fma2(splat(xb0), vr0p, ar0), brp);
        ar1 = add2(fma2(splat(xb1), vr0p, ar1), brp);

        float z00,z01,z10,z11, r00,r01,r10,r11;
        unpack2(az0,z00,z01); unpack2(az1,z10,z11);
        unpack2(ar0,r00,r01); unpack2(ar1,r10,r11);
        z00=sigm(z00); z01=sigm(z01); z10=sigm(z10); z11=sigm(z11);
        r00=sigm(r00); r01=sigm(r01); r10=sigm(r10); r11=sigm(r11);

        *(float2*)(g_hr + gb0*H_ + c0 + jp) = make_float2(ho0.x*r00, ho0.y*r01);
        *(float2*)(g_hr + gb1*H_ + c0 + jp) = make_float2(ho1.x*r10, ho1.y*r11);

        ep++; group_barrier(tileM, tileN, ep);

        // ---- phase 2: h_tilde = tanh([x, h*r, St*k, Mass] @ Wh + bh) ----
        ull ah0a = 0, ah0b = 0, ah1a = 0, ah1b = 0;
        {
            const float* base2 = g_hr + (tileM*32)*H_;
            float4 pf[4];
            #pragma unroll
            for (int u = 0; u < 4; u++){
                int i = tid + u*NTHR; int row = i >> 5, c4 = (i & 31)*4;
                pf[u] = __ldcg((const float4*)(base2 + row*H_ + c4));
            }
            #pragma unroll 1
            for (int ch = 0; ch < NCH; ch++){
                #pragma unroll
                for (int u = 0; u < 4; u++){
                    int i = tid + u*NTHR; int row = i >> 5, c4 = (i & 31)*4;
                    *(float4*)(hS + row*HS_STRIDE + c4) = pf[u];
                }
                __syncthreads();
                if (ch < NCH-1){
                    int kc = (ch+1)*KC;
                    #pragma unroll
                    for (int u = 0; u < 4; u++){
                        int i = tid + u*NTHR; int row = i >> 5, c4 = (i & 31)*4;
                        pf[u] = __ldcg((const float4*)(base2 + row*H_ + kc + c4));
                    }
                }
                const ull* whp = (const ull*)(WhS + ch*KC*32) + p;
                #pragma unroll 4
                for (int kk = 0; kk < KC; kk += 4){
                    float4 ha = *(const float4*)(h0p + kk);
                    float4 hb = *(const float4*)(h1p + kk);
                    ull w;
                    w = whp[(kk+0)*16]; ah0a=fma2(splat(ha.x),w,ah0a); ah1a=fma2(splat(hb.x),w,ah1a);
                    w = whp[(kk+1)*16]; ah0b=fma2(splat(ha.y),w,ah0b); ah1b=fma2(splat(hb.y),w,ah1b);
                    w = whp[(kk+2)*16]; ah0a=fma2(splat(ha.z),w,ah0a); ah1a=fma2(splat(hb.z),w,ah1a);
                    w = whp[(kk+3)*16]; ah0b=fma2(splat(ha.w),w,ah0b); ah1b=fma2(splat(hb.w),w,ah1b);
                }
                __syncthreads();
            }
        }

        const float kv0 = __ldcg(&g_k[gb0]);
        const float kv1 = __ldcg(&g_k[gb1]);

        ull ah0 = add2(ah0a, ah0b), ah1 = add2(ah1a, ah1b);
        ah0 = fma2(splat(xb0),     vh0p,   ah0);
        ah0 = fma2(splat(st0*kv0), vh513p, ah0);
        ah0 = fma2(splat(ms0),     vh514p, ah0);
        ah0 = add2(ah0, bhp);
        ah1 = fma2(splat(xb1),     vh0p,   ah1);
        ah1 = fma2(splat(st1*kv1), vh513p, ah1);
        ah1 = fma2(splat(ms1),     vh514p, ah1);
        ah1 = add2(ah1, bhp);

        float t00,t01,t10,t11;
        unpack2(ah0,t00,t01); unpack2(ah1,t10,t11);
        t00 = tanhf(t00); t01 = tanhf(t01); t10 = tanhf(t10); t11 = tanhf(t11);

        const float hn00 = (1.f - z00)*ho0.x + z00*t00;
        const float hn01 = (1.f - z01)*ho0.y + z01*t01;
        const float hn10 = (1.f - z10)*ho1.x + z10*t10;
        const float hn11 = (1.f - z11)*ho1.y + z11*t11;

        *(float2*)(out + (gb0*T_ + t)*H_ + c0 + jp) = make_float2(hn00, hn01);
        *(float2*)(out + (gb1*T_ + t)*H_ + c0 + jp) = make_float2(hn10, hn11);

        // k partial: sum over this CTA's 32 columns (reduce across the 16 col-pairs)
        float kp0 = hn00*wk0 + hn01*wk1;
        float kp1 = hn10*wk0 + hn11*wk1;
        #pragma unroll
        for (int off = 8; off; off >>= 1){
            kp0 += __shfl_down_sync(0xffffffffu, kp0, off, 16);
            kp1 += __shfl_down_sync(0xffffffffu, kp1, off, 16);
        }
        if (p == 0){
            g_kpart[tileN*B_ + gb0] = kp0;
            g_kpart[tileN*B_ + gb1] = kp1;
        }

        ep++; group_barrier(tileM, tileN, ep);
    }
}

extern "C" void kernel_launch(void* const* d_in, const int* in_sizes, int n_in,
                              void* d_out, int out_size) {
    (void)in_sizes; (void)n_in; (void)out_size;
    const float* inputs = (const float*)d_in[0];
    const float* St     = (const float*)d_in[1];
    const float* Mass   = (const float*)d_in[2];
    const float* Wz     = (const float*)d_in[3];
    const float* bz     = (const float*)d_in[4];
    const float* Wr     = (const float*)d_in[5];
    const float* br     = (const float*)d_in[6];
    const float* Wh     = (const float*)d_in[7];
    const float* bh     = (const float*)d_in[8];
    const float* Wk     = (const float*)d_in[9];
    const float* bk     = (const float*)d_in[10];
    float* out = (float*)d_out;

    cudaFuncSetAttribute(mcgru_kernel, cudaFuncAttributeMaxDynamicSharedMemorySize, SMEM_BYTES);

    init_kernel<<<1, 512>>>();
    mcgru_kernel<<<NCTA, NTHR, SMEM_BYTES>>>(inputs, St, Mass, Wz, bz, Wr, br,
                                             Wh, bh, Wk, bk, out);
}

// round 7
// speedup vs baseline: 1.0980x; 1.0980x over previous
#include <cuda_runtime.h>

typedef unsigned long long ull;

#define B_   256
#define T_   1000
#define H_   512
#define NTN  16          // column tiles (32 cols each)
#define NTM  8           // batch tiles (32 batches each)
#define NCTA (NTN*NTM)   // 128
#define NTHR 256
#define KC   128         // K chunk staged in smem
#define NCH  (H_/KC)     // 4
#define HS_STRIDE 132    // padded row stride (floats) for staged h chunk

// shared memory layout (float offsets)
// W4 layout per matrix: float4 W4[kq][p] = {w[2kq][c0+2p], w[2kq+1][c0+2p],
//                                           w[2kq][c0+2p+1], w[2kq+1][c0+2p+1]}
// i.e. ull.x = (k0,k1) partials for col 2p, ull.y = for col 2p+1.
#define OFF_W4Z   0
#define OFF_W4R   16384
#define OFF_W4H   32768
#define OFF_HS    49152
#define SMEM_FLOATS (OFF_HS + 32*HS_STRIDE)   // 53376
#define SMEM_BYTES (SMEM_FLOATS*4)            // 213504

// persistent device state
__device__ float g_hr[B_*H_];
__device__ float g_k[B_];
__device__ float g_kpart[NTN*B_];
__device__ volatile unsigned g_arrive[NTM*16];
__device__ volatile unsigned g_release[NTM*32];

// ---- packed f32x2 helpers (Blackwell FFMA2 via PTX) ----
__device__ __forceinline__ ull fma2(ull a, ull b, ull c){ ull d; asm("fma.rn.f32x2 %0,%1,%2,%3;":"=l"(d):"l"(a),"l"(b),"l"(c)); return d; }
__device__ __forceinline__ ull add2(ull a, ull b){ ull d; asm("add.rn.f32x2 %0,%1,%2;":"=l"(d):"l"(a),"l"(b)); return d; }
__device__ __forceinline__ void unpack2(ull v, float& lo, float& hi){ asm("mov.b64 {%0,%1},%2;":"=f"(lo),"=f"(hi):"l"(v)); }
__device__ __forceinline__ float hsum2(ull v){ float lo,hi; unpack2(v,lo,hi); return lo+hi; }

__device__ __forceinline__ float sigm(float x){ return 1.0f/(1.0f+__expf(-x)); }
__device__ __forceinline__ float tanh_(float x){ return 2.0f/(1.0f+__expf(-2.0f*x)) - 1.0f; }

// 16-CTA group barrier (per batch-tile group); epoch-based, reset by init_kernel
__device__ __forceinline__ void group_barrier(int grp, int mem, unsigned ep){
    __threadfence();
    __syncthreads();
    if (threadIdx.x == 0){
        if (mem == 0){
            #pragma unroll 1
            for (int i = 1; i < 16; i++){
                while (g_arrive[grp*16 + i] < ep) { }
            }
            __threadfence();
            g_release[grp*32] = ep;
        } else {
            g_arrive[grp*16 + mem] = ep;
            while (g_release[grp*32] < ep) { }
        }
    }
    __syncthreads();
}

__global__ void init_kernel(){
    int i = threadIdx.x;
    if (i < NTM*16) g_arrive[i] = 0u;
    if (i < NTM*32) g_release[i] = 0u;
}

// per-iteration MAC blocks: hreg = ulonglong2, .x = h pair (k0,k1), .y = (k2,k3)
#define P1B(hreg, wz0, wz1, wr0, wr1, AZ, AR) \
    AZ.x = fma2(hreg.x, wz0.x, AZ.x); AZ.y = fma2(hreg.x, wz0.y, AZ.y); \
    AR.x = fma2(hreg.x, wr0.x, AR.x); AR.y = fma2(hreg.x, wr0.y, AR.y); \
    AZ.x = fma2(hreg.y, wz1.x, AZ.x); AZ.y = fma2(hreg.y, wz1.y, AZ.y); \
    AR.x = fma2(hreg.y, wr1.x, AR.x); AR.y = fma2(hreg.y, wr1.y, AR.y);

#define P2B(hreg, w0, w1, AH) \
    AH.x = fma2(hreg.x, w0.x, AH.x); AH.y = fma2(hreg.x, w0.y, AH.y); \
    AH.x = fma2(hreg.y, w1.x, AH.x); AH.y = fma2(hreg.y, w1.y, AH.y);

__global__ void __launch_bounds__(NTHR, 1) mcgru_kernel(
    const float* __restrict__ inp, const float* __restrict__ St, const float* __restrict__ Mass,
    const float* __restrict__ Wz, const float* __restrict__ bz,
    const float* __restrict__ Wr, const float* __restrict__ br,
    const float* __restrict__ Wh, const float* __restrict__ bh,
    const float* __restrict__ Wk, const float* __restrict__ bk,
    float* __restrict__ out)
{
    extern __shared__ float sm[];
    float* hS = sm + OFF_HS;
    const ulonglong2* W4Zu = (const ulonglong2*)(sm + OFF_W4Z);
    const ulonglong2* W4Ru = (const ulonglong2*)(sm + OFF_W4R);
    const ulonglong2* W4Hu = (const ulonglong2*)(sm + OFF_W4H);

    const int tid   = threadIdx.x;
    const int tileN = blockIdx.x & (NTN-1);
    const int tileM = blockIdx.x >> 4;
    const int c0    = tileN * 32;
    const int kh    = tid >> 7;          // k-half 0/1
    const int r7    = tid & 127;
    const int p     = r7 & 15;           // col pair -> cols c0+2p, c0+2p+1
    const int bq    = r7 >> 4;           // 0..7 -> batches 4bq..4bq+3
    const int b0    = bq * 4;
    const int gbase = tileM*32 + b0;

    // ---- prologue: build interleaved weight layout in SMEM ----
    for (int i = tid; i < 4096; i += NTHR){
        int kq = i >> 4, pp = i & 15;
        int c = c0 + 2*pp;
        const float2 z0 = *(const float2*)&Wz[(2*kq+1)*H_ + c];
        const float2 z1 = *(const float2*)&Wz[(2*kq+2)*H_ + c];
        ((float4*)(sm + OFF_W4Z))[i] = make_float4(z0.x, z1.x, z0.y, z1.y);
        const float2 r0 = *(const float2*)&Wr[(2*kq+1)*H_ + c];
        const float2 r1 = *(const float2*)&Wr[(2*kq+2)*H_ + c];
        ((float4*)(sm + OFF_W4R))[i] = make_float4(r0.x, r1.x, r0.y, r1.y);
        const float2 h0 = *(const float2*)&Wh[(2*kq+1)*H_ + c];
        const float2 h1 = *(const float2*)&Wh[(2*kq+2)*H_ + c];
        ((float4*)(sm + OFF_W4H))[i] = make_float4(h0.x, h1.x, h0.y, h1.y);
    }

    // per-thread scalar constants (x-row weights, extra rows, biases)
    const int cc = c0 + 2*p;
    const float2 vz0  = *(const float2*)&Wz[cc];
    const float2 vr0  = *(const float2*)&Wr[cc];
    const float2 vh0  = *(const float2*)&Wh[cc];
    const float2 v513 = *(const float2*)&Wh[513*H_ + cc];
    const float2 v514 = *(const float2*)&Wh[514*H_ + cc];
    const float2 bzf  = *(const float2*)&bz[cc];
    const float2 brf  = *(const float2*)&br[cc];
    const float2 bhf  = *(const float2*)&bh[cc];
    const float2 wkf  = *(const float2*)&Wk[cc];
    const float4 st4  = *(const float4*)&St[gbase];
    const float4 ms4  = *(const float4*)&Mass[gbase];
    const float stA[4] = {st4.x, st4.y, st4.z, st4.w};
    const float msA[4] = {ms4.x, ms4.y, ms4.z, ms4.w};
    __syncthreads();

    float2 ho_[4];  // this thread's own h_{t-1} slice (2 cols x 4 batches)
    #pragma unroll
    for (int i = 0; i < 4; i++) ho_[i] = make_float2(0.f, 0.f);
    float2 z_[4];

    float kreg = 0.0f;   // leader register copy of k (tileN==0, tid<32)
    unsigned ep = 0;

    #pragma unroll 1
    for (int t = 0; t < T_; t++){
        // ---- k finalize: k_{t-1} from partials (leader column-tile) ----
        if (tileN == 0 && tid < 32){
            int gb = tileM*32 + tid;
            if (t == 0){
                kreg = 0.0f;
            } else {
                float s = kreg * __ldg(&Wk[H_]) + __ldg(&bk[0]);
                #pragma unroll
                for (int n = 0; n < NTN; n++) s += __ldcg(&g_kpart[n*B_ + gb]);
                kreg = sigm(s);
            }
            g_k[gb] = kreg;
        }

        float xb[4];
        #pragma unroll
        for (int i = 0; i < 4; i++) xb[i] = __ldg(&inp[(gbase+i)*T_ + t]);

        // ---- phase 1: z, r = sigmoid([x, h_{t-1}] @ W + b) ----
        ulonglong2 az[4], ar[4];
        #pragma unroll
        for (int i = 0; i < 4; i++){ az[i] = make_ulonglong2(0,0); ar[i] = make_ulonglong2(0,0); }

        if (t > 0){
            const float* base1 = out + (size_t)(tileM*32)*(T_*H_) + (size_t)(t-1)*H_;
            float4 pf[4];
            #pragma unroll
            for (int u = 0; u < 4; u++){
                int i = tid + u*NTHR; int row = i >> 5, c4 = (i & 31)*4;
                pf[u] = __ldcg((const float4*)(base1 + (size_t)row*(T_*H_) + c4));
            }
            #pragma unroll 1
            for (int ch = 0; ch < NCH; ch++){
                #pragma unroll
                for (int u = 0; u < 4; u++){
                    int i = tid + u*NTHR; int row = i >> 5, c4 = (i & 31)*4;
                    *(float4*)(hS + row*HS_STRIDE + c4) = pf[u];
                }
                __syncthreads();
                if (ch < NCH-1){
                    int kc = (ch+1)*KC;
                    #pragma unroll
                    for (int u = 0; u < 4; u++){
                        int i = tid + u*NTHR; int row = i >> 5, c4 = (i & 31)*4;
                        pf[u] = __ldcg((const float4*)(base1 + (size_t)row*(T_*H_) + kc + c4));
                    }
                }
                const ulonglong2* wz = W4Zu + (ch*64 + kh*32)*16 + p;
                const ulonglong2* wr = W4Ru + (ch*64 + kh*32)*16 + p;
                const float* hb = hS + kh*64;
                #pragma unroll 2
                for (int it = 0; it < 16; it++){
                    ulonglong2 wz0 = wz[(2*it)*16],   wr0 = wr[(2*it)*16];
                    ulonglong2 wz1 = wz[(2*it+1)*16], wr1 = wr[(2*it+1)*16];
                    ulonglong2 hh0 = *(const ulonglong2*)(hb + (b0+0)*HS_STRIDE + 4*it);
                    ulonglong2 hh1 = *(const ulonglong2*)(hb + (b0+1)*HS_STRIDE + 4*it);
                    ulonglong2 hh2 = *(const ulonglong2*)(hb + (b0+2)*HS_STRIDE + 4*it);
                    ulonglong2 hh3 = *(const ulonglong2*)(hb + (b0+3)*HS_STRIDE + 4*it);
                    P1B(hh0, wz0, wz1, wr0, wr1, az[0], ar[0])
                    P1B(hh1, wz0, wz1, wr0, wr1, az[1], ar[1])
                    P1B(hh2, wz0, wz1, wr0, wr1, az[2], ar[2])
                    P1B(hh3, wz0, wz1, wr0, wr1, az[3], ar[3])
                }
                __syncthreads();
            }
            // cross-half reduction through (now dead) hS region
            ulonglong2* red = (ulonglong2*)hS;
            if (kh){
                int r8 = r7*8;
                red[r8+0]=az[0]; red[r8+1]=az[1]; red[r8+2]=az[2]; red[r8+3]=az[3];
                red[r8+4]=ar[0]; red[r8+5]=ar[1]; red[r8+6]=ar[2]; red[r8+7]=ar[3];
            }
            __syncthreads();
            if (!kh){
                int r8 = r7*8;
                #pragma unroll
                for (int i = 0; i < 4; i++){
                    az[i].x = add2(az[i].x, red[r8+i].x);   az[i].y = add2(az[i].y, red[r8+i].y);
                    ar[i].x = add2(ar[i].x, red[r8+4+i].x); ar[i].y = add2(ar[i].y, red[r8+4+i].y);
                }
            }
        }

        if (!kh){
            #pragma unroll
            for (int i = 0; i < 4; i++){
                float s0 = hsum2(az[i].x) + xb[i]*vz0.x + bzf.x;
                float s1 = hsum2(az[i].y) + xb[i]*vz0.y + bzf.y;
                z_[i] = make_float2(sigm(s0), sigm(s1));
                float q0 = hsum2(ar[i].x) + xb[i]*vr0.x + brf.x;
                float q1 = hsum2(ar[i].y) + xb[i]*vr0.y + brf.y;
                float rr0 = sigm(q0), rr1 = sigm(q1);
                *(float2*)&g_hr[(gbase+i)*H_ + cc] = make_float2(ho_[i].x*rr0, ho_[i].y*rr1);
            }
        }

        ep++; group_barrier(tileM, tileN, ep);

        float4 kv4;
        if (!kh) kv4 = __ldcg((const float4*)&g_k[gbase]);

        // ---- phase 2: h_tilde = tanh([x, h*r, St*k, Mass] @ Wh + bh) ----
        ulonglong2 ah[4];
        #pragma unroll
        for (int i = 0; i < 4; i++) ah[i] = make_ulonglong2(0,0);
        {
            const float* base2 = g_hr + (tileM*32)*H_;
            float4 pf[4];
            #pragma unroll
            for (int u = 0; u < 4; u++){
                int i = tid + u*NTHR; int row = i >> 5, c4 = (i & 31)*4;
                pf[u] = __ldcg((const float4*)(base2 + row*H_ + c4));
            }
            #pragma unroll 1
            for (int ch = 0; ch < NCH; ch++){
                #pragma unroll
                for (int u = 0; u < 4; u++){
                    int i = tid + u*NTHR; int row = i >> 5, c4 = (i & 31)*4;
                    *(float4*)(hS + row*HS_STRIDE + c4) = pf[u];
                }
                __syncthreads();
                if (ch < NCH-1){
                    int kc = (ch+1)*KC;
                    #pragma unroll
                    for (int u = 0; u < 4; u++){
                        int i = tid + u*NTHR; int row = i >> 5, c4 = (i & 31)*4;
                        pf[u] = __ldcg((const float4*)(base2 + row*H_ + kc + c4));
                    }
                }
                const ulonglong2* wh = W4Hu + (ch*64 + kh*32)*16 + p;
                const float* hb = hS + kh*64;
                #pragma unroll 2
                for (int it = 0; it < 16; it++){
                    ulonglong2 w0 = wh[(2*it)*16], w1 = wh[(2*it+1)*16];
                    ulonglong2 hh0 = *(const ulonglong2*)(hb + (b0+0)*HS_STRIDE + 4*it);
                    ulonglong2 hh1 = *(const ulonglong2*)(hb + (b0+1)*HS_STRIDE + 4*it);
                    ulonglong2 hh2 = *(const ulonglong2*)(hb + (b0+2)*HS_STRIDE + 4*it);
                    ulonglong2 hh3 = *(const ulonglong2*)(hb + (b0+3)*HS_STRIDE + 4*it);
                    P2B(hh0, w0, w1, ah[0])
                    P2B(hh1, w0, w1, ah[1])
                    P2B(hh2, w0, w1, ah[2])
                    P2B(hh3, w0, w1, ah[3])
                }
                __syncthreads();
            }
            ulonglong2* red = (ulonglong2*)hS;
            if (kh){
                int r4 = r7*4;
                red[r4+0]=ah[0]; red[r4+1]=ah[1]; red[r4+2]=ah[2]; red[r4+3]=ah[3];
            }
            __syncthreads();
            if (!kh){
                int r4 = r7*4;
                #pragma unroll
                for (int i = 0; i < 4; i++){
                    ah[i].x = add2(ah[i].x, red[r4+i].x); ah[i].y = add2(ah[i].y, red[r4+i].y);
                }
            }
        }

        if (!kh){
            const float kvA[4] = {kv4.x, kv4.y, kv4.z, kv4.w};
            float kp[4];
            #pragma unroll
            for (int i = 0; i < 4; i++){
                float sk = stA[i]*kvA[i];
                float s0 = hsum2(ah[i].x) + xb[i]*vh0.x + sk*v513.x + msA[i]*v514.x + bhf.x;
                float s1 = hsum2(ah[i].y) + xb[i]*vh0.y + sk*v513.y + msA[i]*v514.y + bhf.y;
                float t0 = tanh_(s0), t1 = tanh_(s1);
                float hn0 = (1.f - z_[i].x)*ho_[i].x + z_[i].x*t0;
                float hn1 = (1.f - z_[i].y)*ho_[i].y + z_[i].y*t1;
                *(float2*)&out[((size_t)(gbase+i)*T_ + t)*H_ + cc] = make_float2(hn0, hn1);
                ho_[i] = make_float2(hn0, hn1);
                kp[i] = hn0*wkf.x + hn1*wkf.y;
            }
            #pragma unroll
            for (int off = 8; off; off >>= 1){
                kp[0] += __shfl_down_sync(0xffffffffu, kp[0], off, 16);
                kp[1] += __shfl_down_sync(0xffffffffu, kp[1], off, 16);
                kp[2] += __shfl_down_sync(0xffffffffu, kp[2], off, 16);
                kp[3] += __shfl_down_sync(0xffffffffu, kp[3], off, 16);
            }
            if (p == 0){
                *(float4*)&g_kpart[tileN*B_ + gbase] = make_float4(kp[0], kp[1], kp[2], kp[3]);
            }
        }

        ep++; group_barrier(tileM, tileN, ep);
    }
}

extern "C" void kernel_launch(void* const* d_in, const int* in_sizes, int n_in,
                              void* d_out, int out_size) {
    (void)in_sizes; (void)n_in; (void)out_size;
    const float* inputs = (const float*)d_in[0];
    const float* St     = (const float*)d_in[1];
    const float* Mass   = (const float*)d_in[2];
    const float* Wz     = (const float*)d_in[3];
    const float* bz     = (const float*)d_in[4];
    const float* Wr     = (const float*)d_in[5];
    const float* br     = (const float*)d_in[6];
    const float* Wh     = (const float*)d_in[7];
    const float* bh     = (const float*)d_in[8];
    const float* Wk     = (const float*)d_in[9];
    const float* bk     = (const float*)d_in[10];
    float* out = (float*)d_out;

    cudaFuncSetAttribute(mcgru_kernel, cudaFuncAttributeMaxDynamicSharedMemorySize, SMEM_BYTES);

    init_kernel<<<1, 512>>>();
    mcgru_kernel<<<NCTA, NTHR, SMEM_BYTES>>>(inputs, St, Mass, Wz, bz, Wr, br,
                                             Wh, bh, Wk, bk, out);
}

// round 10
// speedup vs baseline: 1.6598x; 1.5116x over previous
#include <cuda_runtime.h>

typedef unsigned long long ull;

#define B_   256
#define T_   1000
#define H_   512
#define NTN  16          // column tiles (32 cols each)
#define NTM  8           // batch tiles (32 batches each)
#define NCTA (NTN*NTM)   // 128
#define NTHR 512
#define KC   128         // K chunk staged in smem
#define NCH  (H_/KC)     // 4
#define HSS  132         // padded row stride (floats), 16B-aligned rows

// shared memory layout (float offsets)
#define OFF_W4Z 0
#define OFF_W4R 16384
#define OFF_W4H 32768
#define OFF_HS  49152
#define HS_BUF  (32*HSS)                 // 4224 floats per buffer
#define OFF_C   (OFF_HS + 2*HS_BUF)      // 57600
#define SMEM_FLOATS (OFF_C + 352)        // 57952
#define SMEM_BYTES  (SMEM_FLOATS*4)      // 231808 (< 232448 optin max)

// persistent device state (counters reset each launch by init_kernel)
__device__ float g_hr[B_*H_];
__device__ float g_k[B_];
__device__ float g_kpart[NTN*B_];
__device__ unsigned g_cnt[NTM*32];

// ---- packed f32x2 helpers (Blackwell FFMA2 via PTX) ----
__device__ __forceinline__ ull fma2(ull a, ull b, ull c){ ull d; asm("fma.rn.f32x2 %0,%1,%2,%3;":"=l"(d):"l"(a),"l"(b),"l"(c)); return d; }
__device__ __forceinline__ void unpack2(ull v, float& lo, float& hi){ asm("mov.b64 {%0,%1},%2;":"=f"(lo),"=f"(hi):"l"(v)); }
__device__ __forceinline__ float hsum2(ull v){ float lo,hi; unpack2(v,lo,hi); return lo+hi; }

__device__ __forceinline__ float sigm(float x){ return 1.0f/(1.0f+__expf(-x)); }
__device__ __forceinline__ float tanh_(float x){ return 2.0f/(1.0f+__expf(-2.0f*x)) - 1.0f; }

// O(1) group barrier: single monotonic counter per 16-CTA group.
// release-arrive via REDG (fire-and-forget), acquire-poll on one cacheline.
__device__ __forceinline__ void group_barrier(unsigned* cnt, unsigned target){
    __syncthreads();
    if (threadIdx.x == 0){
        asm volatile("red.release.gpu.global.add.u32 [%0], 1;" :: "l"(cnt) : "memory");
        unsigned v;
        do { asm volatile("ld.acquire.gpu.global.u32 %0, [%1];" : "=r"(v) : "l"(cnt) : "memory"); } while (v < target);
    }
    __syncthreads();
}

__global__ void init_kernel(){
    int i = threadIdx.x;
    if (i < NTM*32) g_cnt[i] = 0u;
}

// MAC blocks: hreg = ulonglong2, .x = h pair (k0,k1), .y = (k2,k3)
#define P1B(hreg, wz0, wz1, wr0, wr1, AZ, AR) \
    AZ.x = fma2(hreg.x, wz0.x, AZ.x); AZ.y = fma2(hreg.x, wz0.y, AZ.y); \
    AR.x = fma2(hreg.x, wr0.x, AR.x); AR.y = fma2(hreg.x, wr0.y, AR.y); \
    AZ.x = fma2(hreg.y, wz1.x, AZ.x); AZ.y = fma2(hreg.y, wz1.y, AZ.y); \
    AR.x = fma2(hreg.y, wr1.x, AR.x); AR.y = fma2(hreg.y, wr1.y, AR.y);

#define P2B(hreg, w0, w1, AH) \
    AH.x = fma2(hreg.x, w0.x, AH.x); AH.y = fma2(hreg.x, w0.y, AH.y); \
    AH.x = fma2(hreg.y, w1.x, AH.x); AH.y = fma2(hreg.y, w1.y, AH.y);

__global__ void __launch_bounds__(NTHR, 1) mcgru_kernel(
    const float* __restrict__ inp, const float* __restrict__ St, const float* __restrict__ Mass,
    const float* __restrict__ Wz, const float* __restrict__ bz,
    const float* __restrict__ Wr, const float* __restrict__ br,
    const float* __restrict__ Wh, const float* __restrict__ bh,
    const float* __restrict__ Wk, const float* __restrict__ bk,
    float* __restrict__ out)
{
    extern __shared__ float sm[];
    float* hS0 = sm + OFF_HS;
    float* hS1 = sm + OFF_HS + HS_BUF;
    float* red = sm + OFF_HS;            // alias over both buffers
    float* cs  = sm + OFF_C;             // epilogue constants
    const ulonglong2* W4Zu = (const ulonglong2*)(sm + OFF_W4Z);
    const ulonglong2* W4Ru = (const ulonglong2*)(sm + OFF_W4R);
    const ulonglong2* W4Hu = (const ulonglong2*)(sm + OFF_W4H);

    const int tid   = threadIdx.x;
    const int tileN = blockIdx.x & (NTN-1);
    const int tileM = blockIdx.x >> 4;
    const int c0    = tileN * 32;
    const int kh    = tid >> 7;          // k-quarter 0..3
    const int r7    = tid & 127;
    const int p     = r7 & 15;           // col pair -> cols c0+2p, c0+2p+1
    const int bq    = r7 >> 4;           // 0..7 -> batches 4bq..4bq+3
    const int b0    = bq * 4;
    const int gbase = tileM*32 + b0;
    const int jp    = 2*p;
    const int cc    = c0 + jp;
    unsigned* cnt   = &g_cnt[tileM*32];

    // ---- prologue: interleaved weight layout in SMEM ----
    // W4[kq][pp] = {w[2kq][c0+2pp], w[2kq+1][c0+2pp], w[2kq][c0+2pp+1], w[2kq+1][c0+2pp+1]}
    for (int i = tid; i < 4096; i += NTHR){
        int kq = i >> 4, pp = i & 15;
        int c = c0 + 2*pp;
        const float2 z0 = *(const float2*)&Wz[(2*kq+1)*H_ + c];
        const float2 z1 = *(const float2*)&Wz[(2*kq+2)*H_ + c];
        ((float4*)(sm + OFF_W4Z))[i] = make_float4(z0.x, z1.x, z0.y, z1.y);
        const float2 r0 = *(const float2*)&Wr[(2*kq+1)*H_ + c];
        const float2 r1 = *(const float2*)&Wr[(2*kq+2)*H_ + c];
        ((float4*)(sm + OFF_W4R))[i] = make_float4(r0.x, r1.x, r0.y, r1.y);
        const float2 h0 = *(const float2*)&Wh[(2*kq+1)*H_ + c];
        const float2 h1 = *(const float2*)&Wh[(2*kq+2)*H_ + c];
        ((float4*)(sm + OFF_W4H))[i] = make_float4(h0.x, h1.x, h0.y, h1.y);
    }
    if (tid < 32){
        cs[tid]       = Wz[c0 + tid];            // vz0
        cs[32 + tid]  = Wr[c0 + tid];            // vr0
        cs[64 + tid]  = Wh[c0 + tid];            // vh0
        cs[96 + tid]  = Wh[513*H_ + c0 + tid];   // v513
        cs[128 + tid] = Wh[514*H_ + c0 + tid];   // v514
        cs[160 + tid] = bz[c0 + tid];
        cs[192 + tid] = br[c0 + tid];
        cs[224 + tid] = bh[c0 + tid];
        cs[256 + tid] = Wk[c0 + tid];
        cs[288 + tid] = St[tileM*32 + tid];
        cs[320 + tid] = Mass[tileM*32 + tid];
    }
    __syncthreads();

    float2 ho_[4], z_[4];
    #pragma unroll
    for (int i = 0; i < 4; i++) ho_[i] = make_float2(0.f, 0.f);

    float kreg = 0.0f;
    unsigned bar = 0;

    #pragma unroll 1
    for (int t = 0; t < T_; t++){
        // ---- k finalize from step t-1 partials (leader column-tile) ----
        if (tileN == 0 && tid < 32){
            int gb = tileM*32 + tid;
            if (t == 0){
                kreg = 0.0f;
            } else {
                float s = kreg * __ldg(&Wk[H_]) + __ldg(&bk[0]);
                #pragma unroll
                for (int n = 0; n < NTN; n++) s += __ldcg(&g_kpart[n*B_ + gb]);
                kreg = sigm(s);
            }
            g_k[gb] = kreg;
        }

        float xb[4];
        if (kh == 0){
            #pragma unroll
            for (int i = 0; i < 4; i++) xb[i] = __ldg(&inp[(gbase+i)*T_ + t]);
        }

        // ---- phase 1: z, r = sigmoid([x, h_{t-1}] @ W + b) ----
        float s1[16];
        if (t > 0){
            ulonglong2 az[4], ar[4];
            #pragma unroll
            for (int i = 0; i < 4; i++){ az[i] = make_ulonglong2(0,0); ar[i] = make_ulonglong2(0,0); }

            const float* base1 = out + (size_t)(tileM*32)*(T_*H_) + (size_t)(t-1)*H_;
            float4 pf[2];
            #pragma unroll
            for (int u = 0; u < 2; u++){
                int i = tid + u*NTHR; int row = i >> 5, c4 = (i & 31)*4;
                pf[u] = __ldcg((const float4*)(base1 + (size_t)row*(T_*H_) + c4));
            }
            #pragma unroll 1
            for (int ch = 0; ch < NCH; ch++){
                float* buf = (ch & 1) ? hS1 : hS0;
                #pragma unroll
                for (int u = 0; u < 2; u++){
                    int i = tid + u*NTHR; int row = i >> 5, c4 = (i & 31)*4;
                    *(float4*)(buf + row*HSS + c4) = pf[u];
                }
                __syncthreads();
                if (ch < NCH-1){
                    int kc = (ch+1)*KC;
                    #pragma unroll
                    for (int u = 0; u < 2; u++){
                        int i = tid + u*NTHR; int row = i >> 5, c4 = (i & 31)*4;
                        pf[u] = __ldcg((const float4*)(base1 + (size_t)row*(T_*H_) + kc + c4));
                    }
                }
                const ulonglong2* wz = W4Zu + (ch*64 + kh*16)*16 + p;
                const ulonglong2* wr = W4Ru + (ch*64 + kh*16)*16 + p;
                const float* hb = buf + kh*32;
                #pragma unroll 4
                for (int it = 0; it < 8; it++){
                    ulonglong2 wz0 = wz[(2*it)*16],   wr0 = wr[(2*it)*16];
                    ulonglong2 wz1 = wz[(2*it+1)*16], wr1 = wr[(2*it+1)*16];
                    ulonglong2 hh0 = *(const ulonglong2*)(hb + (b0+0)*HSS + 4*it);
                    ulonglong2 hh1 = *(const ulonglong2*)(hb + (b0+1)*HSS + 4*it);
                    ulonglong2 hh2 = *(const ulonglong2*)(hb + (b0+2)*HSS + 4*it);
                    ulonglong2 hh3 = *(const ulonglong2*)(hb + (b0+3)*HSS + 4*it);
                    P1B(hh0, wz0, wz1, wr0, wr1, az[0], ar[0])
                    P1B(hh1, wz0, wz1, wr0, wr1, az[1], ar[1])
                    P1B(hh2, wz0, wz1, wr0, wr1, az[2], ar[2])
                    P1B(hh3, wz0, wz1, wr0, wr1, az[3], ar[3])
                }
            }
            __syncthreads();   // all MAC reads done before red overwrites hS0/hS1
            if (kh){
                int base = (kh-1)*128 + r7;
                #pragma unroll
                for (int i = 0; i < 4; i++){
                    red[(2*i+0)*384 + base]   = hsum2(az[i].x);
                    red[(2*i+1)*384 + base]   = hsum2(az[i].y);
                    red[(8+2*i+0)*384 + base] = hsum2(ar[i].x);
                    red[(8+2*i+1)*384 + base] = hsum2(ar[i].y);
                }
            }
            __syncthreads();
            if (!kh){
                #pragma unroll
                for (int i = 0; i < 4; i++){
                    s1[2*i]     = hsum2(az[i].x); s1[2*i+1]   = hsum2(az[i].y);
                    s1[8+2*i]   = hsum2(ar[i].x); s1[8+2*i+1] = hsum2(ar[i].y);
                }
                #pragma unroll
                for (int j = 0; j < 16; j++)
                    s1[j] += red[j*384 + r7] + red[j*384 + 128 + r7] + red[j*384 + 256 + r7];
            }
        } else if (!kh){
            #pragma unroll
            for (int j = 0; j < 16; j++) s1[j] = 0.f;
        }

        if (!kh){
            const float2 vz0 = *(const float2*)(cs + jp);
            const float2 vr0 = *(const float2*)(cs + 32 + jp);
            const float2 bzf = *(const float2*)(cs + 160 + jp);
            const float2 brf = *(const float2*)(cs + 192 + jp);
            #pragma unroll
            for (int i = 0; i < 4; i++){
                float z0 = sigm(s1[2*i]   + xb[i]*vz0.x + bzf.x);
                float z1 = sigm(s1[2*i+1] + xb[i]*vz0.y + bzf.y);
                z_[i] = make_float2(z0, z1);
                float r0 = sigm(s1[8+2*i]   + xb[i]*vr0.x + brf.x);
                float r1 = sigm(s1[8+2*i+1] + xb[i]*vr0.y + brf.y);
                *(float2*)&g_hr[(gbase+i)*H_ + cc] = make_float2(ho_[i].x*r0, ho_[i].y*r1);
            }
        }

        bar++; group_barrier(cnt, bar*16);

        float4 kv4 = make_float4(0.f,0.f,0.f,0.f);
        if (!kh) kv4 = __ldcg((const float4*)&g_k[gbase]);

        // ---- phase 2: h_tilde = tanh([x, h*r, St*k, Mass] @ Wh + bh) ----
        float s2[8];
        {
            ulonglong2 ah[4];
            #pragma unroll
            for (int i = 0; i < 4; i++) ah[i] = make_ulonglong2(0,0);

            const float* base2 = g_hr + (tileM*32)*H_;
            float4 pf[2];
            #pragma unroll
            for (int u = 0; u < 2; u++){
                int i = tid + u*NTHR; int row = i >> 5, c4 = (i & 31)*4;
                pf[u] = __ldcg((const float4*)(base2 + row*H_ + c4));
            }
            #pragma unroll 1
            for (int ch = 0; ch < NCH; ch++){
                float* buf = (ch & 1) ? hS1 : hS0;
                #pragma unroll
                for (int u = 0; u < 2; u++){
                    int i = tid + u*NTHR; int row = i >> 5, c4 = (i & 31)*4;
                    *(float4*)(buf + row*HSS + c4) = pf[u];
                }
                __syncthreads();
                if (ch < NCH-1){
                    int kc = (ch+1)*KC;
                    #pragma unroll
                    for (int u = 0; u < 2; u++){
                        int i = tid + u*NTHR; int row = i >> 5, c4 = (i & 31)*4;
                        pf[u] = __ldcg((const float4*)(base2 + row*H_ + kc + c4));
                    }
                }
                const ulonglong2* wh = W4Hu + (ch*64 + kh*16)*16 + p;
                const float* hb = buf + kh*32;
                #pragma unroll 4
                for (int it = 0; it < 8; it++){
                    ulonglong2 w0 = wh[(2*it)*16], w1 = wh[(2*it+1)*16];
                    ulonglong2 hh0 = *(const ulonglong2*)(hb + (b0+0)*HSS + 4*it);
                    ulonglong2 hh1 = *(const ulonglong2*)(hb + (b0+1)*HSS + 4*it);
                    ulonglong2 hh2 = *(const ulonglong2*)(hb + (b0+2)*HSS + 4*it);
                    ulonglong2 hh3 = *(const ulonglong2*)(hb + (b0+3)*HSS + 4*it);
                    P2B(hh0, w0, w1, ah[0])
                    P2B(hh1, w0, w1, ah[1])
                    P2B(hh2, w0, w1, ah[2])
                    P2B(hh3, w0, w1, ah[3])
                }
            }
            // last MAC read buf = hS1; red region below uses hS0 only -> disjoint
            if (kh){
                int base = (kh-1)*128 + r7;
                #pragma unroll
                for (int i = 0; i < 4; i++){
                    red[(2*i+0)*384 + base] = hsum2(ah[i].x);
                    red[(2*i+1)*384 + base] = hsum2(ah[i].y);
                }
            }
            __syncthreads();
            if (!kh){
                #pragma unroll
                for (int i = 0; i < 4; i++){
                    s2[2*i]   = hsum2(ah[i].x);
                    s2[2*i+1] = hsum2(ah[i].y);
                }
                #pragma unroll
                for (int j = 0; j < 8; j++)
                    s2[j] += red[j*384 + r7] + red[j*384 + 128 + r7] + red[j*384 + 256 + r7];
            }
        }

        if (!kh){
            const float2 vh0  = *(const float2*)(cs + 64 + jp);
            const float2 v513 = *(const float2*)(cs + 96 + jp);
            const float2 v514 = *(const float2*)(cs + 128 + jp);
            const float2 bhf  = *(const float2*)(cs + 224 + jp);
            const float2 wkf  = *(const float2*)(cs + 256 + jp);
            const float kvA[4] = {kv4.x, kv4.y, kv4.z, kv4.w};
            float kp[4];
            #pragma unroll
            for (int i = 0; i < 4; i++){
                float st_i = cs[288 + b0 + i];
                float ms_i = cs[320 + b0 + i];
                float sk = st_i * kvA[i];
                float a0 = s2[2*i]   + xb[i]*vh0.x + sk*v513.x + ms_i*v514.x + bhf.x;
                float a1 = s2[2*i+1] + xb[i]*vh0.y + sk*v513.y + ms_i*v514.y + bhf.y;
                float t0 = tanh_(a0), t1 = tanh_(a1);
                float hn0 = (1.f - z_[i].x)*ho_[i].x + z_[i].x*t0;
                float hn1 = (1.f - z_[i].y)*ho_[i].y + z_[i].y*t1;
                *(float2*)&out[((size_t)(gbase+i)*T_ + t)*H_ + cc] = make_float2(hn0, hn1);
                ho_[i] = make_float2(hn0, hn1);
                kp[i] = hn0*wkf.x + hn1*wkf.y;
            }
            #pragma unroll
            for (int off = 8; off; off >>= 1){
                kp[0] += __shfl_down_sync(0xffffffffu, kp[0], off, 16);
                kp[1] += __shfl_down_sync(0xffffffffu, kp[1], off, 16);
                kp[2] += __shfl_down_sync(0xffffffffu, kp[2], off, 16);
                kp[3] += __shfl_down_sync(0xffffffffu, kp[3], off, 16);
            }
            if (p == 0){
                *(float4*)&g_kpart[tileN*B_ + gbase] = make_float4(kp[0], kp[1], kp[2], kp[3]);
            }
        }

        bar++; group_barrier(cnt, bar*16);
    }
}

extern "C" void kernel_launch(void* const* d_in, const int* in_sizes, int n_in,
                              void* d_out, int out_size) {
    (void)in_sizes; (void)n_in; (void)out_size;
    const float* inputs = (const float*)d_in[0];
    const float* St     = (const float*)d_in[1];
    const float* Mass   = (const float*)d_in[2];
    const float* Wz     = (const float*)d_in[3];
    const float* bz     = (const float*)d_in[4];
    const float* Wr     = (const float*)d_in[5];
    const float* br     = (const float*)d_in[6];
    const float* Wh     = (const float*)d_in[7];
    const float* bh     = (const float*)d_in[8];
    const float* Wk     = (const float*)d_in[9];
    const float* bk     = (const float*)d_in[10];
    float* out = (float*)d_out;

    cudaFuncSetAttribute(mcgru_kernel, cudaFuncAttributeMaxDynamicSharedMemorySize, SMEM_BYTES);

    init_kernel<<<1, 256>>>();
    mcgru_kernel<<<NCTA, NTHR, SMEM_BYTES>>>(inputs, St, Mass, Wz, bz, Wr, br,
                                             Wh, bh, Wk, bk, out);
}